// round 6
// baseline (speedup 1.0000x reference)
#include <cuda_runtime.h>

#define NB      32
#define NIN     1034
#define NOUT    512
#define STRIDE  1088
#define KNS     1000.0f
#define MINW    (-0.3678794411714423f)
#define EF      2.718281828459045f
#define NBUCK   2048

// packed per-batch sorted data: (t, e^t, t*e^t, idx-as-int-bits)
__device__ float4 g_pack[NB * STRIDE];

__device__ __forceinline__ float get_t(const float* __restrict__ x,
                                       const float* __restrict__ pulse,
                                       int b, int i) {
    return (i < 1024) ? x[b * 1024 + i] : pulse[i - 1024];
}

__device__ __forceinline__ int bucket_of(float t) {
    int bid = (int)(t * (float)NBUCK);
    return bid < 0 ? 0 : (bid >= NBUCK ? NBUCK - 1 : bid);
}

// ---------------------------------------------------------------------------
// Kernel 1: per-batch bucket sort + pack.  grid=NB, block=1024.
// ---------------------------------------------------------------------------
__global__ void sort_pack_kernel(const float* __restrict__ x,
                                 const float* __restrict__ pulse) {
    __shared__ int cnt [NBUCK];
    __shared__ int base[NBUCK];
    __shared__ unsigned long long keys[NIN];
    __shared__ float wsum[32];

    const int b   = blockIdx.x;
    const int tid = threadIdx.x;
    const int lane = tid & 31, wid = tid >> 5;

    cnt[tid] = 0; cnt[tid + 1024] = 0;
    __syncthreads();

    for (int i = tid; i < NIN; i += 1024) {
        const float t = get_t(x, pulse, b, i);
        atomicAdd(&cnt[bucket_of(t)], 1);
    }
    __syncthreads();

    {
        const int v0 = cnt[2 * tid], v1 = cnt[2 * tid + 1];
        float s = (float)(v0 + v1);
        #pragma unroll
        for (int off = 1; off < 32; off <<= 1) {
            const float u = __shfl_up_sync(0xffffffffu, s, off);
            if (lane >= off) s += u;
        }
        if (lane == 31) wsum[wid] = s;
        __syncthreads();
        if (wid == 0) {
            float ws = wsum[lane];
            #pragma unroll
            for (int off = 1; off < 32; off <<= 1) {
                const float u = __shfl_up_sync(0xffffffffu, ws, off);
                if (lane >= off) ws += u;
            }
            wsum[lane] = ws;
        }
        __syncthreads();
        const int incl = (int)s + (wid ? (int)wsum[wid - 1] : 0);
        const int excl = incl - v0 - v1;
        base[2 * tid]     = excl;
        base[2 * tid + 1] = excl + v0;
        __syncthreads();
        cnt[2 * tid]     = excl;
        cnt[2 * tid + 1] = excl + v0;
    }
    __syncthreads();

    for (int i = tid; i < NIN; i += 1024) {
        const float t = get_t(x, pulse, b, i);
        const int pos = atomicAdd(&cnt[bucket_of(t)], 1);
        keys[pos] = ((unsigned long long)__float_as_uint(t) << 32) | (unsigned)i;
    }
    __syncthreads();

    for (int bk = tid; bk < NBUCK; bk += 1024) {
        const int s0 = base[bk];
        const int s1 = (bk + 1 < NBUCK) ? base[bk + 1] : NIN;
        for (int i = s0 + 1; i < s1; ++i) {
            const unsigned long long v = keys[i];
            int j = i - 1;
            while (j >= s0 && keys[j] > v) { keys[j + 1] = keys[j]; --j; }
            keys[j + 1] = v;
        }
    }
    __syncthreads();

    for (int i = tid; i < STRIDE; i += 1024) {
        if (i < NIN) {
            const unsigned long long v = keys[i];
            const float t = __uint_as_float((unsigned)(v >> 32));
            const int idx = (int)(unsigned)v;
            const float z = expf(t);
            g_pack[b * STRIDE + i] = make_float4(t, z, z * t, __int_as_float(idx));
        } else {
            g_pack[b * STRIDE + i] = make_float4(KNS, 0.0f, 0.0f, 0.0f);
        }
    }
}

// packed f32x2 helpers (Blackwell)
__device__ __forceinline__ unsigned long long pack2(float lo, float hi) {
    unsigned long long r;
    asm("mov.b64 %0, {%1, %2};" : "=l"(r) : "f"(lo), "f"(hi));
    return r;
}
__device__ __forceinline__ void unpack2(unsigned long long v, float& lo, float& hi) {
    asm("mov.b64 {%0, %1}, %2;" : "=f"(lo), "=f"(hi) : "l"(v));
}
__device__ __forceinline__ unsigned long long addf32x2(unsigned long long a,
                                                       unsigned long long b) {
    unsigned long long r;
    asm("add.rn.f32x2 %0, %1, %2;" : "=l"(r) : "l"(a), "l"(b));
    return r;
}

// ---------------------------------------------------------------------------
// Kernel 2: one warp per (batch, out-neuron). Packed f32x2 warp scan,
// log-prefilter, 2-iteration Lambert W (good init + fast + accurate polish).
// ---------------------------------------------------------------------------
__global__ void solve_kernel(const float* __restrict__ W,
                             float* __restrict__ out) {
    const int gw   = (int)((blockIdx.x * blockDim.x + threadIdx.x) >> 5);
    const int lane = threadIdx.x & 31;
    const int b    = gw >> 9;
    const int o    = gw & 511;

    const float4* __restrict__ pk   = g_pack + b * STRIDE;
    const float*  __restrict__ wrow = W + o * NIN;

    unsigned long long carry = pack2(0.0f, 0.0f);
    float result = KNS;
    bool  done = false;

    for (int k0 = 0; k0 < NIN && !done; k0 += 32) {
        const int k = k0 + lane;
        const float4 p = pk[k];
        const float t = p.x;
        const float w = wrow[__float_as_int(p.w)];

        // packed (A, B) inclusive warp scan
        unsigned long long ab = pack2(w * p.y, w * p.z);
        #pragma unroll
        for (int off = 1; off < 32; off <<= 1) {
            const unsigned long long u = __shfl_up_sync(0xffffffffu, ab, off);
            if (lane >= off) ab = addf32x2(ab, u);
        }
        const unsigned long long tot = __shfl_sync(0xffffffffu, ab, 31);
        const unsigned long long cum = addf32x2(carry, ab);

        float A, B;
        unpack2(cum, A, B);

        const bool  Apos  = A > 1e-10f;
        const float Asafe = Apos ? A : 1.0f;
        const float boa   = __fdividef(B, Asafe);

        float nxt = __shfl_down_sync(0xffffffffu, t, 1);
        if (lane == 31) nxt = pk[k0 + 32].x;

        // cheap prefilter: arg >= -1/e  <=>  ln(A) >= B/A + 1  (0.02 margin)
        const bool quick = Apos && (__logf(Asafe) >= boa + 0.98f);

        if (__ballot_sync(0xffffffffu, quick)) {
            float tc = 0.0f;
            bool valid = false;
            if (quick) {
                // accurate arg (reference formula)
                const float arg = -__fdividef(1.0f, Asafe) * expf(fminf(boa, 80.0f));
                if (arg >= MINW) {
                    const float xw = fmaxf(fminf(arg, 0.0f), MINW);
                    float wv;
                    if (xw < -0.25f) {
                        // 3-term branch-point series: w = -1 + p - p^2/3 + 11p^3/72
                        const float pbr = sqrtf(fmaxf(2.0f * (1.0f + EF * xw), 0.0f));
                        wv = -1.0f + pbr * (1.0f + pbr * (-0.33333333f + pbr * 0.15277778f));
                    } else {
                        // 3-term Taylor: w = x - x^2 + 1.5 x^3
                        wv = xw * (1.0f - xw * (1.0f - 1.5f * xw));
                    }
                    {   // 1 fast Halley step (MUFU exp, fast div)
                        const float ew = __expf(wv);
                        const float f  = wv * ew - xw;
                        const float denom = ew * (wv + 1.0f)
                                  - __fdividef((wv + 2.0f) * f,
                                               2.0f * (wv + 1.0f) + 1e-12f);
                        wv = wv - __fdividef(f, denom + 1e-12f);
                    }
                    {   // 1 accurate polish step (lands on the reference fixpoint)
                        const float ew = expf(wv);
                        const float f  = wv * ew - xw;
                        const float denom = ew * (wv + 1.0f)
                                  - (wv + 2.0f) * f / (2.0f * (wv + 1.0f) + 1e-12f);
                        wv = wv - f / (denom + 1e-12f);
                    }
                    tc = boa - wv;
                    valid = (t < KNS) && (tc >= t) && (tc <= nxt);
                }
            }
            const unsigned vm = __ballot_sync(0xffffffffu, valid);
            if (vm) {
                const int src = __ffs((int)vm) - 1;
                result = __shfl_sync(0xffffffffu, tc, src);
                done = true;
            }
        }
        carry = addf32x2(carry, tot);
    }

    if (lane == 0) out[b * NOUT + o] = result;
}

// ---------------------------------------------------------------------------
extern "C" void kernel_launch(void* const* d_in, const int* in_sizes, int n_in,
                              void* d_out, int out_size) {
    const float* x      = (const float*)d_in[0];   // [32, 1024]
    const float* weight = (const float*)d_in[1];   // [512, 1034]
    const float* pulse  = (const float*)d_in[2];   // [10]
    float* out = (float*)d_out;                    // [32, 512]

    sort_pack_kernel<<<NB, 1024>>>(x, pulse);

    const int warps = NB * NOUT;
    solve_kernel<<<warps / 8, 256>>>(weight, out);
}

// round 7
// speedup vs baseline: 1.0935x; 1.0935x over previous
#include <cuda_runtime.h>

#define NB      32
#define NIN     1034
#define NOUT    512
#define STRIDE  1088
#define KNS     1000.0f
#define MINW    (-0.3678794411714423f)
#define EF      2.718281828459045f
#define NBUCK   2048

// packed per-batch sorted data: (t, e^t, t*e^t, idx-as-int-bits)
__device__ float4 g_pack[NB * STRIDE];

__device__ __forceinline__ float get_t(const float* __restrict__ x,
                                       const float* __restrict__ pulse,
                                       int b, int i) {
    return (i < 1024) ? x[b * 1024 + i] : pulse[i - 1024];
}

__device__ __forceinline__ int bucket_of(float t) {
    int bid = (int)(t * (float)NBUCK);
    return bid < 0 ? 0 : (bid >= NBUCK ? NBUCK - 1 : bid);
}

// ---------------------------------------------------------------------------
// Kernel 1: per-batch bucket sort + pack.  grid=NB, block=1024.
// ---------------------------------------------------------------------------
__global__ void sort_pack_kernel(const float* __restrict__ x,
                                 const float* __restrict__ pulse) {
    __shared__ int cnt [NBUCK];
    __shared__ int base[NBUCK];
    __shared__ unsigned long long keys[NIN];
    __shared__ float wsum[32];

    const int b   = blockIdx.x;
    const int tid = threadIdx.x;
    const int lane = tid & 31, wid = tid >> 5;

    cnt[tid] = 0; cnt[tid + 1024] = 0;
    __syncthreads();

    for (int i = tid; i < NIN; i += 1024) {
        const float t = get_t(x, pulse, b, i);
        atomicAdd(&cnt[bucket_of(t)], 1);
    }
    __syncthreads();

    {
        const int v0 = cnt[2 * tid], v1 = cnt[2 * tid + 1];
        float s = (float)(v0 + v1);
        #pragma unroll
        for (int off = 1; off < 32; off <<= 1) {
            const float u = __shfl_up_sync(0xffffffffu, s, off);
            if (lane >= off) s += u;
        }
        if (lane == 31) wsum[wid] = s;
        __syncthreads();
        if (wid == 0) {
            float ws = wsum[lane];
            #pragma unroll
            for (int off = 1; off < 32; off <<= 1) {
                const float u = __shfl_up_sync(0xffffffffu, ws, off);
                if (lane >= off) ws += u;
            }
            wsum[lane] = ws;
        }
        __syncthreads();
        const int incl = (int)s + (wid ? (int)wsum[wid - 1] : 0);
        const int excl = incl - v0 - v1;
        base[2 * tid]     = excl;
        base[2 * tid + 1] = excl + v0;
        __syncthreads();
        cnt[2 * tid]     = excl;
        cnt[2 * tid + 1] = excl + v0;
    }
    __syncthreads();

    for (int i = tid; i < NIN; i += 1024) {
        const float t = get_t(x, pulse, b, i);
        const int pos = atomicAdd(&cnt[bucket_of(t)], 1);
        keys[pos] = ((unsigned long long)__float_as_uint(t) << 32) | (unsigned)i;
    }
    __syncthreads();

    for (int bk = tid; bk < NBUCK; bk += 1024) {
        const int s0 = base[bk];
        const int s1 = (bk + 1 < NBUCK) ? base[bk + 1] : NIN;
        for (int i = s0 + 1; i < s1; ++i) {
            const unsigned long long v = keys[i];
            int j = i - 1;
            while (j >= s0 && keys[j] > v) { keys[j + 1] = keys[j]; --j; }
            keys[j + 1] = v;
        }
    }
    __syncthreads();

    for (int i = tid; i < STRIDE; i += 1024) {
        if (i < NIN) {
            const unsigned long long v = keys[i];
            const float t = __uint_as_float((unsigned)(v >> 32));
            const int idx = (int)(unsigned)v;
            const float z = expf(t);
            g_pack[b * STRIDE + i] = make_float4(t, z, z * t, __int_as_float(idx));
        } else {
            g_pack[b * STRIDE + i] = make_float4(KNS, 0.0f, 0.0f, 0.0f);
        }
    }
}

// packed f32x2 helpers (Blackwell)
__device__ __forceinline__ unsigned long long pack2(float lo, float hi) {
    unsigned long long r;
    asm("mov.b64 %0, {%1, %2};" : "=l"(r) : "f"(lo), "f"(hi));
    return r;
}
__device__ __forceinline__ void unpack2(unsigned long long v, float& lo, float& hi) {
    asm("mov.b64 {%0, %1}, %2;" : "=f"(lo), "=f"(hi) : "l"(v));
}
__device__ __forceinline__ unsigned long long addf32x2(unsigned long long a,
                                                       unsigned long long b) {
    unsigned long long r;
    asm("add.rn.f32x2 %0, %1, %2;" : "=l"(r) : "l"(a), "l"(b));
    return r;
}

// ---------------------------------------------------------------------------
// Kernel 2: one warp per (batch, out-neuron).
// Window validity decided analytically via g(t) = A*t - B - e^t sign tests
// (no Lambert per chunk). Lambert W computed ONCE, on the winning lane.
// ---------------------------------------------------------------------------
__global__ void solve_kernel(const float* __restrict__ W,
                             float* __restrict__ out) {
    const int gw   = (int)((blockIdx.x * blockDim.x + threadIdx.x) >> 5);
    const int lane = threadIdx.x & 31;
    const int b    = gw >> 9;
    const int o    = gw & 511;

    const float4* __restrict__ pk   = g_pack + b * STRIDE;
    const float*  __restrict__ wrow = W + o * NIN;

    unsigned long long carry = pack2(0.0f, 0.0f);
    float result = KNS;
    bool  done = false;

    for (int k0 = 0; k0 < NIN && !done; k0 += 32) {
        const int k = k0 + lane;
        const float4 p = pk[k];
        const float t = p.x;
        const float z = p.y;                       // z = e^t exactly as packed
        const float w = wrow[__float_as_int(p.w)];

        // packed (A, B) inclusive warp scan
        unsigned long long ab = pack2(w * z, w * p.z);
        #pragma unroll
        for (int off = 1; off < 32; off <<= 1) {
            const unsigned long long u = __shfl_up_sync(0xffffffffu, ab, off);
            if (lane >= off) ab = addf32x2(ab, u);
        }
        const unsigned long long tot = __shfl_sync(0xffffffffu, ab, 31);
        const unsigned long long cum = addf32x2(carry, ab);
        float A, B;
        unpack2(cum, A, B);

        // next (t, z) in one packed shfl; lane 31 reads the next chunk head
        unsigned long long ntz = __shfl_down_sync(0xffffffffu, pack2(t, z), 1);
        float nt, nz;
        unpack2(ntz, nt, nz);
        if (lane == 31) { const float4 q = pk[k0 + 32]; nt = q.x; nz = q.y; }

        bool valid = false;
        if (A > 1e-10f) {
            const float lnA = __logf(A);
            const float boa = __fdividef(B, A);
            const bool reach = lnA >= boa + 1.0f;          // g(lnA) >= 0  (arg >= -1/e)
            const bool lower = fmaf(A, t,  -B) <= z;       // g(t_k)   <= 0  (t* >= t_k)
            const bool upper = (nt >= lnA) ||
                               (fmaf(A, nt, -B) >= nz);    // t* <= t_{k+1}
            valid = reach && lower && upper && (t < KNS);
        }

        const unsigned vm = __ballot_sync(0xffffffffu, valid);
        if (vm) {
            const int src = __ffs((int)vm) - 1;
            float tc = 0.0f;
            if (lane == src) {
                // ONE Lambert solve per (b,o): accurate arg + series init + 3 Halley
                const float boa = B / A;
                float xw = -1.0f / A * expf(fminf(boa, 80.0f));
                xw = fmaxf(fminf(xw, 0.0f), MINW);
                float wv;
                if (xw < -0.25f) {
                    const float pbr = sqrtf(fmaxf(2.0f * (1.0f + EF * xw), 0.0f));
                    wv = -1.0f + pbr * (1.0f + pbr * (-0.33333333f + pbr * 0.15277778f));
                } else {
                    wv = xw * (1.0f - xw * (1.0f - 1.5f * xw));
                }
                #pragma unroll
                for (int it = 0; it < 3; ++it) {
                    const float ew = expf(wv);
                    const float f  = wv * ew - xw;
                    const float denom = ew * (wv + 1.0f)
                              - (wv + 2.0f) * f / (2.0f * (wv + 1.0f) + 1e-12f);
                    wv = wv - f / (denom + 1e-12f);
                }
                tc = boa - wv;
            }
            result = __shfl_sync(0xffffffffu, tc, src);
            done = true;
        }
        carry = addf32x2(carry, tot);
    }

    if (lane == 0) out[b * NOUT + o] = result;
}

// ---------------------------------------------------------------------------
extern "C" void kernel_launch(void* const* d_in, const int* in_sizes, int n_in,
                              void* d_out, int out_size) {
    const float* x      = (const float*)d_in[0];   // [32, 1024]
    const float* weight = (const float*)d_in[1];   // [512, 1034]
    const float* pulse  = (const float*)d_in[2];   // [10]
    float* out = (float*)d_out;                    // [32, 512]

    sort_pack_kernel<<<NB, 1024>>>(x, pulse);

    const int warps = NB * NOUT;
    solve_kernel<<<warps / 8, 256>>>(weight, out);
}